// round 12
// baseline (speedup 1.0000x reference)
#include <cuda_runtime.h>
#include <math.h>
#include <stdint.h>

// ---------------- problem constants ----------------
#define BATCH 32
#define HQ    32
#define KVH   8
#define GQ    4           // HQ / KVH
#define D_HEAD 128
#define HID   4096
#define QKV_COLS 6144     // (H + 2*KVH) * D_HEAD
#define WIN   4096
#define NSPLIT 16
#define PAIRS (BATCH*KVH) // 256
#define KS    8           // GEMM K-split
#define KSEG  (HID/KS)    // 512
#define TKTILES (KSEG/32) // 16 k-tiles of 32 per CTA

// ---------------- device scratch (no allocations allowed) ----------------
__device__ float g_ctx[BATCH * HID];            // attention output, row-major [b][h*128+d]
__device__ float g_xp [KS * BATCH * QKV_COLS];  // qkv gemm partials per K-split
__device__ float g_op [KS * BATCH * HID];       // wo  gemm partials per K-split
__device__ float g_q  [BATCH * HQ  * D_HEAD];   // rope'd q  [b][h][d]
__device__ float g_k  [BATCH * KVH * D_HEAD];   // rope'd new k [b][kv][d]
__device__ float g_v  [BATCH * KVH * D_HEAD];   // new v
__device__ float g_pl [PAIRS * NSPLIT * GQ];
__device__ float g_pa [PAIRS * NSPLIT * GQ * D_HEAD];

// ---------------- PTX helpers ----------------
__device__ __forceinline__ uint32_t f2tf32(float f) {
    uint32_t r;
    asm("cvt.rna.tf32.f32 %0, %1;" : "=r"(r) : "f"(f));
    return r;
}
__device__ __forceinline__ void mma_tf32(float& c0, float& c1, float& c2, float& c3,
                                         uint32_t a0, uint32_t a1, uint32_t a2, uint32_t a3,
                                         uint32_t b0, uint32_t b1) {
    asm("mma.sync.aligned.m16n8k8.row.col.f32.tf32.tf32.f32 "
        "{%0,%1,%2,%3},{%4,%5,%6,%7},{%8,%9},{%0,%1,%2,%3};"
        : "+f"(c0), "+f"(c1), "+f"(c2), "+f"(c3)
        : "r"(a0), "r"(a1), "r"(a2), "r"(a3), "r"(b0), "r"(b1));
}
__device__ __forceinline__ void cp16(void* dst, const void* src) {
    uint32_t d = (uint32_t)__cvta_generic_to_shared(dst);
    asm volatile("cp.async.cg.shared.global [%0], [%1], 16;" :: "r"(d), "l"(src));
}
__device__ __forceinline__ void cp_commit() {
    asm volatile("cp.async.commit_group;" ::: "memory");
}
template <int N>
__device__ __forceinline__ void cp_wait() {
    asm volatile("cp.async.wait_group %0;" :: "n"(N) : "memory");
}

// ---------------- 1) tf32 tensor-core GEMM, 3-stage pipeline, N-tile 64 ---
// Y_part[ks][32][NCOL] = A[32][kseg] @ W[kseg][NCOL].
// CTA: 256 thr = 8 warps (2 m x 4 n), CTA tile 32 x 64, K-tile 32.
// Grid: (NCOL/64, KS) -> wo 512 CTAs, qkv 768 CTAs (occupancy fix).
#define SMB_PITCH 72
#define SMA_PITCH 36
#define SMB_STG   (32 * SMB_PITCH)   // 2304
#define SMA_STG   (32 * SMA_PITCH)   // 1152
#define SMEM_GEMM ((3 * SMB_STG + 3 * SMA_STG) * 4)   // 41472 bytes

__global__ void __launch_bounds__(256, 4) k_gemm_tc(const float* __restrict__ A,
                                                    const float* __restrict__ W,
                                                    float* __restrict__ Yp,
                                                    int NCOL) {
    extern __shared__ float sm[];
    float* sB = sm;                      // [3][32][72]
    float* sA = sm + 3 * SMB_STG;        // [3][32][36]

    const int tid  = threadIdx.x, lane = tid & 31, w = tid >> 5;
    const int n0   = blockIdx.x * 64;
    const int kbase = blockIdx.y * KSEG;
    const int mw = w & 1, nw = w >> 1;
    const int gid = lane >> 2, tig = lane & 3;

    // B: 32 k-rows x 64 n = 512 float4 (2 per thread); A: 256 float4 (1 per thread)
    const int br = tid >> 4, bc4 = (tid & 15) << 2;
    const int ar = tid >> 3, aj  = (tid & 7) << 2;

#define LOAD_TILE(T, S)                                                        \
    {                                                                          \
        const int k0 = kbase + (T) * 32;                                       \
        const float* wsrc = W + (size_t)k0 * NCOL + n0;                        \
        float* bd = sB + (S) * SMB_STG;                                        \
        cp16(bd + br * SMB_PITCH + bc4,        wsrc + (size_t)br * NCOL + bc4);\
        cp16(bd + (br + 16) * SMB_PITCH + bc4,                                 \
             wsrc + (size_t)(br + 16) * NCOL + bc4);                           \
        cp16(sA + (S) * SMA_STG + ar * SMA_PITCH + aj, A + ar * HID + k0 + aj);\
    }

    float c0[2], c1[2], c2[2], c3[2];
#pragma unroll
    for (int j = 0; j < 2; ++j) { c0[j] = c1[j] = c2[j] = c3[j] = 0.f; }

    LOAD_TILE(0, 0);
    cp_commit();
    LOAD_TILE(1, 1);
    cp_commit();

#pragma unroll 1
    for (int t = 0; t < TKTILES; ++t) {
        if (t + 1 < TKTILES) cp_wait<1>(); else cp_wait<0>();
        __syncthreads();
        if (t + 2 < TKTILES) {
            LOAD_TILE(t + 2, (t + 2) % 3);
            cp_commit();
        }

        const int st = t % 3;
        const float* bb = sB + st * SMB_STG;
        const float* aa = sA + st * SMA_STG;

#pragma unroll
        for (int s8 = 0; s8 < 4; ++s8) {
            const int kc = 8 * s8;
            const int rA = (mw * 16 + gid) * SMA_PITCH + kc + tig;
            uint32_t A0 = f2tf32(aa[rA]);
            uint32_t A1 = f2tf32(aa[rA + 8 * SMA_PITCH]);
            uint32_t A2 = f2tf32(aa[rA + 4]);
            uint32_t A3 = f2tf32(aa[rA + 8 * SMA_PITCH + 4]);
#pragma unroll
            for (int j = 0; j < 2; ++j) {
                const int nn = nw * 16 + j * 8 + gid;
                uint32_t B0 = f2tf32(bb[(kc + tig) * SMB_PITCH + nn]);
                uint32_t B1 = f2tf32(bb[(kc + tig + 4) * SMB_PITCH + nn]);
                mma_tf32(c0[j], c1[j], c2[j], c3[j], A0, A1, A2, A3, B0, B1);
            }
        }
    }

    float* Y = Yp + (size_t)blockIdx.y * BATCH * NCOL;
    const int row = mw * 16 + gid;
#pragma unroll
    for (int j = 0; j < 2; ++j) {
        const int col = n0 + nw * 16 + j * 8 + 2 * tig;
        *(float2*)&Y[(size_t)row * NCOL + col]       = make_float2(c0[j], c1[j]);
        *(float2*)&Y[(size_t)(row + 8) * NCOL + col] = make_float2(c2[j], c3[j]);
    }
}

// ---------------- 2) RoPE: one thread per rotation pair -------------------
#define RPE_HEADS ((HQ + KVH) * 64)             // 2560 pair-slots per batch row
#define RPE_PAIRS (BATCH * RPE_HEADS)           // 81920
#define RPE_V     (BATCH * KVH * D_HEAD)        // 32768
#define RPE_TOT   (RPE_PAIRS + RPE_V)           // 114688

__device__ __forceinline__ float psum_x(int i) {
    float s = 0.f;
#pragma unroll
    for (int k = 0; k < KS; ++k) s += g_xp[k * BATCH * QKV_COLS + i];
    return s;
}
__global__ void k_rope(const float* __restrict__ cosc,
                       const float* __restrict__ sinc,
                       const int* __restrict__ sp_p) {
    int i = blockIdx.x * blockDim.x + threadIdx.x;   // RPE_TOT threads
    int sp = *sp_p;
    if (i < RPE_PAIRS) {
        int m = i / RPE_HEADS;
        int r = i - m * RPE_HEADS;        // h*64 + d
        int h = r >> 6, d = r & 63;
        int c = h * D_HEAD + d;
        float a  = psum_x(m * QKV_COLS + c);
        float bb = psum_x(m * QKV_COLS + c + 64);
        float cs0 = cosc[sp * D_HEAD + d],      sn0 = sinc[sp * D_HEAD + d];
        float cs1 = cosc[sp * D_HEAD + d + 64], sn1 = sinc[sp * D_HEAD + d + 64];
        float o0 = a * cs0 - bb * sn0;    // rot[d]    = -u[d+64]
        float o1 = bb * cs1 + a * sn1;    // rot[d+64] =  u[d]
        if (h < HQ) {
            g_q[m * (HQ * D_HEAD) + c]      = o0;
            g_q[m * (HQ * D_HEAD) + c + 64] = o1;
        } else {
            int cc = (h - HQ) * D_HEAD + d;
            g_k[m * (KVH * D_HEAD) + cc]      = o0;
            g_k[m * (KVH * D_HEAD) + cc + 64] = o1;
        }
    } else {
        int j = i - RPE_PAIRS;            // v element
        int m = j >> 10, cc = j & 1023;   // KVH*D_HEAD = 1024
        g_v[m * (KVH * D_HEAD) + cc] = psum_x(m * QKV_COLS + (HQ + KVH) * D_HEAD + cc);
    }
}

// ---------------- 3) flash-decode partials: 2 rows/iter, streaming loads --
__global__ void __launch_bounds__(256, 3) k_attn_part(const float* __restrict__ CK,
                                                      const float* __restrict__ CV,
                                                      const int* __restrict__ sp_p) {
    const int split = blockIdx.x;
    const int pair  = blockIdx.y;            // b*8 + kv
    const int b  = pair >> 3;
    const int kv = pair & 7;
    const int Lr = *sp_p;                    // 3000 cache rows
    const int rows = (Lr + NSPLIT - 1) / NSPLIT;
    const int lo = split * rows;
    const int hi = min(lo + rows, Lr);
    const int tid = threadIdx.x, lane = tid & 31, w = tid >> 5;
    const bool g1 = (lane & 1), g2 = (lane & 2);

    float4 q0 = *(const float4*)&g_q[((b * HQ) + kv * GQ + 0) * D_HEAD + 4 * lane];
    float4 q1 = *(const float4*)&g_q[((b * HQ) + kv * GQ + 1) * D_HEAD + 4 * lane];
    float4 q2 = *(const float4*)&g_q[((b * HQ) + kv * GQ + 2) * D_HEAD + 4 * lane];
    float4 q3 = *(const float4*)&g_q[((b * HQ) + kv * GQ + 3) * D_HEAD + 4 * lane];

    const float4* Kb = (const float4*)(CK + (size_t)pair * WIN * D_HEAD);
    const float4* Vb = (const float4*)(CV + (size_t)pair * WIN * D_HEAD);

    float4 acc0, acc1, acc2, acc3;
    acc0.x=acc0.y=acc0.z=acc0.w=0.f; acc1=acc0; acc2=acc0; acc3=acc0;
    float lsum = 0.f;
    const float scale = 0.08838834764831845f;   // 1/sqrt(128)

    int base = lo + 2 * w;
    if (base < hi) {
        const float4* kp = Kb + (size_t)base * 32 + lane;
        const float4* vp = Vb + (size_t)base * 32 + lane;
        int ob = (base + 1 < hi) ? 32 : 0;
        float4 ka = __ldcs(kp),       va = __ldcs(vp);
        float4 kb4 = __ldcs(kp + ob), vb4 = __ldcs(vp + ob);
        while (true) {
            const bool more = (base + 16) < hi;
            float4 kna, vna, knb, vnb;
            if (more) {
                int o2 = (base + 17 < hi) ? 544 : 512;
                kna = __ldcs(kp + 512); vna = __ldcs(vp + 512);
                knb = __ldcs(kp + o2);  vnb = __ldcs(vp + o2);
            }

            float a0 = q0.x*ka.x + q0.y*ka.y + q0.z*ka.z + q0.w*ka.w;
            float a1 = q1.x*ka.x + q1.y*ka.y + q1.z*ka.z + q1.w*ka.w;
            float a2 = q2.x*ka.x + q2.y*ka.y + q2.z*ka.z + q2.w*ka.w;
            float a3 = q3.x*ka.x + q3.y*ka.y + q3.z*ka.z + q3.w*ka.w;
            float b0 = q0.x*kb4.x + q0.y*kb4.y + q0.z*kb4.z + q0.w*kb4.w;
            float b1 = q1.x*kb4.x + q1.y*kb4.y + q1.z*kb4.z + q1.w*kb4.w;
            float b2 = q2.x*kb4.x + q2.y*kb4.y + q2.z*kb4.z + q2.w*kb4.w;
            float b3 = q3.x*kb4.x + q3.y*kb4.y + q3.z*kb4.z + q3.w*kb4.w;
            a0 += __shfl_xor_sync(0xffffffffu, a0, 1);
            a1 += __shfl_xor_sync(0xffffffffu, a1, 1);
            a2 += __shfl_xor_sync(0xffffffffu, a2, 1);
            a3 += __shfl_xor_sync(0xffffffffu, a3, 1);
            b0 += __shfl_xor_sync(0xffffffffu, b0, 1);
            b1 += __shfl_xor_sync(0xffffffffu, b1, 1);
            b2 += __shfl_xor_sync(0xffffffffu, b2, 1);
            b3 += __shfl_xor_sync(0xffffffffu, b3, 1);
            a0 += __shfl_xor_sync(0xffffffffu, a0, 2);
            a1 += __shfl_xor_sync(0xffffffffu, a1, 2);
            a2 += __shfl_xor_sync(0xffffffffu, a2, 2);
            a3 += __shfl_xor_sync(0xffffffffu, a3, 2);
            b0 += __shfl_xor_sync(0xffffffffu, b0, 2);
            b1 += __shfl_xor_sync(0xffffffffu, b1, 2);
            b2 += __shfl_xor_sync(0xffffffffu, b2, 2);
            b3 += __shfl_xor_sync(0xffffffffu, b3, 2);
            float tA = g1 ? a1 : a0;
            float tB = g1 ? a3 : a2;
            float sa = g2 ? tB : tA;
            float uA = g1 ? b1 : b0;
            float uB = g1 ? b3 : b2;
            float sb = g2 ? uB : uA;
            sa += __shfl_xor_sync(0xffffffffu, sa, 4);
            sb += __shfl_xor_sync(0xffffffffu, sb, 4);
            sa += __shfl_xor_sync(0xffffffffu, sa, 8);
            sb += __shfl_xor_sync(0xffffffffu, sb, 8);
            sa += __shfl_xor_sync(0xffffffffu, sa, 16);
            sb += __shfl_xor_sync(0xffffffffu, sb, 16);
            float pa = __expf(sa * scale);
            float pb = (base + 1 < hi) ? __expf(sb * scale) : 0.f;
            lsum += pa + pb;
            float pa0 = __shfl_sync(0xffffffffu, pa, 0, 4);
            float pa1 = __shfl_sync(0xffffffffu, pa, 1, 4);
            float pa2 = __shfl_sync(0xffffffffu, pa, 2, 4);
            float pa3 = __shfl_sync(0xffffffffu, pa, 3, 4);
            float pb0 = __shfl_sync(0xffffffffu, pb, 0, 4);
            float pb1 = __shfl_sync(0xffffffffu, pb, 1, 4);
            float pb2 = __shfl_sync(0xffffffffu, pb, 2, 4);
            float pb3 = __shfl_sync(0xffffffffu, pb, 3, 4);
            acc0.x += pa0*va.x + pb0*vb4.x;  acc0.y += pa0*va.y + pb0*vb4.y;
            acc0.z += pa0*va.z + pb0*vb4.z;  acc0.w += pa0*va.w + pb0*vb4.w;
            acc1.x += pa1*va.x + pb1*vb4.x;  acc1.y += pa1*va.y + pb1*vb4.y;
            acc1.z += pa1*va.z + pb1*vb4.z;  acc1.w += pa1*va.w + pb1*vb4.w;
            acc2.x += pa2*va.x + pb2*vb4.x;  acc2.y += pa2*va.y + pb2*vb4.y;
            acc2.z += pa2*va.z + pb2*vb4.z;  acc2.w += pa2*va.w + pb2*vb4.w;
            acc3.x += pa3*va.x + pb3*vb4.x;  acc3.y += pa3*va.y + pb3*vb4.y;
            acc3.z += pa3*va.z + pb3*vb4.z;  acc3.w += pa3*va.w + pb3*vb4.w;

            if (!more) break;
            base += 16; kp += 512; vp += 512;
            ka = kna; va = vna; kb4 = knb; vb4 = vnb;
        }
    }

    __shared__ float4 sA4[8][GQ][32];
    __shared__ float  sL[8][GQ];
    sA4[w][0][lane] = acc0;
    sA4[w][1][lane] = acc1;
    sA4[w][2][lane] = acc2;
    sA4[w][3][lane] = acc3;
    if (lane < 4) sL[w][lane] = lsum;
    __syncthreads();

    const int obase = (pair * NSPLIT + split) * GQ;
    {
        const int half = tid >> 7;
        const int d    = tid & 127;
#pragma unroll
        for (int g = half; g < GQ; g += 2) {
            float A = 0.f;
#pragma unroll
            for (int ww = 0; ww < 8; ++ww)
                A += ((const float*)&sA4[ww][g][0])[d];
            g_pa[(obase + g) * D_HEAD + d] = A;
        }
        if (tid < 4) {
            float z = 0.f;
#pragma unroll
            for (int ww = 0; ww < 8; ++ww) z += sL[ww][tid];
            g_pl[obase + tid] = z;
        }
    }
}

// ---------------- 4) combine splits + new-token row -> ctx ---------------
// One warp per (pair, group); lanes = float4 d-chunks, 16 unrolled loads.
__global__ void __launch_bounds__(256) k_attn_red() {
    const int W    = blockIdx.x * 8 + (threadIdx.x >> 5);   // (pair, g)
    const int lane = threadIdx.x & 31;
    const int pair = W >> 2, g = W & 3;
    const int b = pair >> 3, kv = pair & 7;

    float4 qv = *(const float4*)&g_q[((b * HQ) + kv * GQ + g) * D_HEAD + 4 * lane];
    float4 kn = *(const float4*)&g_k[pair * D_HEAD + 4 * lane];
    float s = qv.x*kn.x + qv.y*kn.y + qv.z*kn.z + qv.w*kn.w;
#pragma unroll
    for (int off = 16; off > 0; off >>= 1)
        s += __shfl_xor_sync(0xffffffffu, s, off);
    const float p = __expf(s * 0.08838834764831845f);

    float4 vn = *(const float4*)&g_v[pair * D_HEAD + 4 * lane];
    float Z = p;
    float4 A = make_float4(p * vn.x, p * vn.y, p * vn.z, p * vn.w);
#pragma unroll
    for (int sp = 0; sp < NSPLIT; ++sp) {
        int idx = (pair * NSPLIT + sp) * GQ + g;
        Z += g_pl[idx];
        float4 t = *(const float4*)&g_pa[idx * D_HEAD + 4 * lane];
        A.x += t.x; A.y += t.y; A.z += t.z; A.w += t.w;
    }
    const float inv = 1.f / Z;
    const int c = (kv * GQ + g) * D_HEAD + 4 * lane;
    *(float4*)&g_ctx[b * HID + c] = make_float4(A.x*inv, A.y*inv, A.z*inv, A.w*inv);
}

// ---------------- 5) sum wo K-split partials into the output (float4) -----
__global__ void k_addout(float* __restrict__ out) {
    int i = blockIdx.x * blockDim.x + threadIdx.x;   // BATCH*HID/4 threads
    float4 s = make_float4(0.f, 0.f, 0.f, 0.f);
#pragma unroll
    for (int k = 0; k < KS; ++k) {
        float4 t = *(const float4*)&g_op[k * BATCH * HID + 4 * i];
        s.x += t.x; s.y += t.y; s.z += t.z; s.w += t.w;
    }
    *(float4*)&out[4 * i] = s;
}

// ---------------- launch ----------------
extern "C" void kernel_launch(void* const* d_in, const int* in_sizes, int n_in,
                              void* d_out, int out_size) {
    const float* x    = (const float*)d_in[0];
    const float* wqkv = (const float*)d_in[1];
    const float* wo   = (const float*)d_in[2];
    const float* ck   = (const float*)d_in[3];
    const float* cv   = (const float*)d_in[4];
    const float* cosc = (const float*)d_in[5];
    const float* sinc = (const float*)d_in[6];
    // d_in[7] = attn_mask: equivalent to (pos <= start_pos), applied analytically
    const int* sp = (const int*)d_in[8];
    // d_in[9] = current_pos (== start_pos; new-token row handled in k_attn_red)
    float* out = (float*)d_out;

    static bool attr_set = false;
    if (!attr_set) {
        cudaFuncSetAttribute(k_gemm_tc,
                             cudaFuncAttributeMaxDynamicSharedMemorySize,
                             SMEM_GEMM);
        attr_set = true;
    }

    float* ctx; float* xp; float* op;
    cudaGetSymbolAddress((void**)&ctx, g_ctx);
    cudaGetSymbolAddress((void**)&xp,  g_xp);
    cudaGetSymbolAddress((void**)&op,  g_op);

    dim3 gq(QKV_COLS / 64, KS);
    k_gemm_tc<<<gq, 256, SMEM_GEMM>>>(x, wqkv, xp, QKV_COLS);
    k_rope<<<RPE_TOT / 256, 256>>>(cosc, sinc, sp);
    dim3 ag(NSPLIT, PAIRS);
    k_attn_part<<<ag, 256>>>(ck, cv, sp);
    k_attn_red<<<(PAIRS * GQ) / 8, 256>>>();
    dim3 go(HID / 64, KS);
    k_gemm_tc<<<go, 256, SMEM_GEMM>>>(ctx, wo, op, HID);
    k_addout<<<(BATCH * HID) / 1024, 256>>>(out);
}

// round 13
// speedup vs baseline: 1.0037x; 1.0037x over previous
#include <cuda_runtime.h>
#include <math.h>
#include <stdint.h>

// ---------------- problem constants ----------------
#define BATCH 32
#define HQ    32
#define KVH   8
#define GQ    4           // HQ / KVH
#define D_HEAD 128
#define HID   4096
#define QKV_COLS 6144     // (H + 2*KVH) * D_HEAD
#define WIN   4096
#define NSPLIT 16
#define PAIRS (BATCH*KVH) // 256
#define KS    8           // GEMM K-split
#define KSEG  (HID/KS)    // 512
#define TKTILES (KSEG/32) // 16 k-tiles of 32 per CTA

// ---------------- device scratch (no allocations allowed) ----------------
__device__ float g_ctx[BATCH * HID];            // attention output, row-major [b][h*128+d]
__device__ float g_xp [KS * BATCH * QKV_COLS];  // qkv gemm partials per K-split
__device__ float g_op [KS * BATCH * HID];       // wo  gemm partials per K-split
__device__ float g_q  [BATCH * HQ  * D_HEAD];   // rope'd q  [b][h][d]
__device__ float g_k  [BATCH * KVH * D_HEAD];   // rope'd new k [b][kv][d]
__device__ float g_v  [BATCH * KVH * D_HEAD];   // new v
__device__ float g_pl [PAIRS * NSPLIT * GQ];
__device__ float g_pa [PAIRS * NSPLIT * GQ * D_HEAD];

// ---------------- PTX helpers ----------------
__device__ __forceinline__ uint32_t f2tf32(float f) {
    uint32_t r;
    asm("cvt.rna.tf32.f32 %0, %1;" : "=r"(r) : "f"(f));
    return r;
}
__device__ __forceinline__ void mma_tf32(float& c0, float& c1, float& c2, float& c3,
                                         uint32_t a0, uint32_t a1, uint32_t a2, uint32_t a3,
                                         uint32_t b0, uint32_t b1) {
    asm("mma.sync.aligned.m16n8k8.row.col.f32.tf32.tf32.f32 "
        "{%0,%1,%2,%3},{%4,%5,%6,%7},{%8,%9},{%0,%1,%2,%3};"
        : "+f"(c0), "+f"(c1), "+f"(c2), "+f"(c3)
        : "r"(a0), "r"(a1), "r"(a2), "r"(a3), "r"(b0), "r"(b1));
}
__device__ __forceinline__ void cp16(void* dst, const void* src) {
    uint32_t d = (uint32_t)__cvta_generic_to_shared(dst);
    asm volatile("cp.async.cg.shared.global [%0], [%1], 16;" :: "r"(d), "l"(src));
}
__device__ __forceinline__ void cp_commit() {
    asm volatile("cp.async.commit_group;" ::: "memory");
}
template <int N>
__device__ __forceinline__ void cp_wait() {
    asm volatile("cp.async.wait_group %0;" :: "n"(N) : "memory");
}

// ---------------- 1) tf32 tensor-core GEMM, 3-stage pipeline, N-tile 64 ---
// Y_part[ks][32][NCOL] = A[32][kseg] @ W[kseg][NCOL].
// CTA: 256 thr = 8 warps (2 m x 4 n), CTA tile 32 x 64, K-tile 32.
// Grid: (NCOL/64, KS) -> wo 512 CTAs, qkv 768 CTAs (occupancy fix).
#define SMB_PITCH 72
#define SMA_PITCH 36
#define SMB_STG   (32 * SMB_PITCH)   // 2304
#define SMA_STG   (32 * SMA_PITCH)   // 1152
#define SMEM_GEMM ((3 * SMB_STG + 3 * SMA_STG) * 4)   // 41472 bytes

__global__ void __launch_bounds__(256, 4) k_gemm_tc(const float* __restrict__ A,
                                                    const float* __restrict__ W,
                                                    float* __restrict__ Yp,
                                                    int NCOL) {
    extern __shared__ float sm[];
    float* sB = sm;                      // [3][32][72]
    float* sA = sm + 3 * SMB_STG;        // [3][32][36]

    const int tid  = threadIdx.x, lane = tid & 31, w = tid >> 5;
    const int n0   = blockIdx.x * 64;
    const int kbase = blockIdx.y * KSEG;
    const int mw = w & 1, nw = w >> 1;
    const int gid = lane >> 2, tig = lane & 3;

    // B: 32 k-rows x 64 n = 512 float4 (2 per thread); A: 256 float4 (1 per thread)
    const int br = tid >> 4, bc4 = (tid & 15) << 2;
    const int ar = tid >> 3, aj  = (tid & 7) << 2;

#define LOAD_TILE(T, S)                                                        \
    {                                                                          \
        const int k0 = kbase + (T) * 32;                                       \
        const float* wsrc = W + (size_t)k0 * NCOL + n0;                        \
        float* bd = sB + (S) * SMB_STG;                                        \
        cp16(bd + br * SMB_PITCH + bc4,        wsrc + (size_t)br * NCOL + bc4);\
        cp16(bd + (br + 16) * SMB_PITCH + bc4,                                 \
             wsrc + (size_t)(br + 16) * NCOL + bc4);                           \
        cp16(sA + (S) * SMA_STG + ar * SMA_PITCH + aj, A + ar * HID + k0 + aj);\
    }

    float c0[2], c1[2], c2[2], c3[2];
#pragma unroll
    for (int j = 0; j < 2; ++j) { c0[j] = c1[j] = c2[j] = c3[j] = 0.f; }

    LOAD_TILE(0, 0);
    cp_commit();
    LOAD_TILE(1, 1);
    cp_commit();

#pragma unroll 1
    for (int t = 0; t < TKTILES; ++t) {
        if (t + 1 < TKTILES) cp_wait<1>(); else cp_wait<0>();
        __syncthreads();
        if (t + 2 < TKTILES) {
            LOAD_TILE(t + 2, (t + 2) % 3);
            cp_commit();
        }

        const int st = t % 3;
        const float* bb = sB + st * SMB_STG;
        const float* aa = sA + st * SMA_STG;

#pragma unroll
        for (int s8 = 0; s8 < 4; ++s8) {
            const int kc = 8 * s8;
            const int rA = (mw * 16 + gid) * SMA_PITCH + kc + tig;
            uint32_t A0 = f2tf32(aa[rA]);
            uint32_t A1 = f2tf32(aa[rA + 8 * SMA_PITCH]);
            uint32_t A2 = f2tf32(aa[rA + 4]);
            uint32_t A3 = f2tf32(aa[rA + 8 * SMA_PITCH + 4]);
#pragma unroll
            for (int j = 0; j < 2; ++j) {
                const int nn = nw * 16 + j * 8 + gid;
                uint32_t B0 = f2tf32(bb[(kc + tig) * SMB_PITCH + nn]);
                uint32_t B1 = f2tf32(bb[(kc + tig + 4) * SMB_PITCH + nn]);
                mma_tf32(c0[j], c1[j], c2[j], c3[j], A0, A1, A2, A3, B0, B1);
            }
        }
    }

    float* Y = Yp + (size_t)blockIdx.y * BATCH * NCOL;
    const int row = mw * 16 + gid;
#pragma unroll
    for (int j = 0; j < 2; ++j) {
        const int col = n0 + nw * 16 + j * 8 + 2 * tig;
        *(float2*)&Y[(size_t)row * NCOL + col]       = make_float2(c0[j], c1[j]);
        *(float2*)&Y[(size_t)(row + 8) * NCOL + col] = make_float2(c2[j], c3[j]);
    }
}

// ---------------- 2) RoPE: one thread per rotation pair -------------------
#define RPE_HEADS ((HQ + KVH) * 64)             // 2560 pair-slots per batch row
#define RPE_PAIRS (BATCH * RPE_HEADS)           // 81920
#define RPE_V     (BATCH * KVH * D_HEAD)        // 32768
#define RPE_TOT   (RPE_PAIRS + RPE_V)           // 114688

__device__ __forceinline__ float psum_x(int i) {
    float s = 0.f;
#pragma unroll
    for (int k = 0; k < KS; ++k) s += g_xp[k * BATCH * QKV_COLS + i];
    return s;
}
__global__ void k_rope(const float* __restrict__ cosc,
                       const float* __restrict__ sinc,
                       const int* __restrict__ sp_p) {
    int i = blockIdx.x * blockDim.x + threadIdx.x;   // RPE_TOT threads
    int sp = *sp_p;
    if (i < RPE_PAIRS) {
        int m = i / RPE_HEADS;
        int r = i - m * RPE_HEADS;        // h*64 + d
        int h = r >> 6, d = r & 63;
        int c = h * D_HEAD + d;
        float a  = psum_x(m * QKV_COLS + c);
        float bb = psum_x(m * QKV_COLS + c + 64);
        float cs0 = cosc[sp * D_HEAD + d],      sn0 = sinc[sp * D_HEAD + d];
        float cs1 = cosc[sp * D_HEAD + d + 64], sn1 = sinc[sp * D_HEAD + d + 64];
        float o0 = a * cs0 - bb * sn0;    // rot[d]    = -u[d+64]
        float o1 = bb * cs1 + a * sn1;    // rot[d+64] =  u[d]
        if (h < HQ) {
            g_q[m * (HQ * D_HEAD) + c]      = o0;
            g_q[m * (HQ * D_HEAD) + c + 64] = o1;
        } else {
            int cc = (h - HQ) * D_HEAD + d;
            g_k[m * (KVH * D_HEAD) + cc]      = o0;
            g_k[m * (KVH * D_HEAD) + cc + 64] = o1;
        }
    } else {
        int j = i - RPE_PAIRS;            // v element
        int m = j >> 10, cc = j & 1023;   // KVH*D_HEAD = 1024
        g_v[m * (KVH * D_HEAD) + cc] = psum_x(m * QKV_COLS + (HQ + KVH) * D_HEAD + cc);
    }
}

// ---------------- 3) flash-decode partials: 2 rows/iter, streaming loads --
__global__ void __launch_bounds__(256, 3) k_attn_part(const float* __restrict__ CK,
                                                      const float* __restrict__ CV,
                                                      const int* __restrict__ sp_p) {
    const int split = blockIdx.x;
    const int pair  = blockIdx.y;            // b*8 + kv
    const int b  = pair >> 3;
    const int kv = pair & 7;
    const int Lr = *sp_p;                    // 3000 cache rows
    const int rows = (Lr + NSPLIT - 1) / NSPLIT;
    const int lo = split * rows;
    const int hi = min(lo + rows, Lr);
    const int tid = threadIdx.x, lane = tid & 31, w = tid >> 5;
    const bool g1 = (lane & 1), g2 = (lane & 2);

    float4 q0 = *(const float4*)&g_q[((b * HQ) + kv * GQ + 0) * D_HEAD + 4 * lane];
    float4 q1 = *(const float4*)&g_q[((b * HQ) + kv * GQ + 1) * D_HEAD + 4 * lane];
    float4 q2 = *(const float4*)&g_q[((b * HQ) + kv * GQ + 2) * D_HEAD + 4 * lane];
    float4 q3 = *(const float4*)&g_q[((b * HQ) + kv * GQ + 3) * D_HEAD + 4 * lane];

    const float4* Kb = (const float4*)(CK + (size_t)pair * WIN * D_HEAD);
    const float4* Vb = (const float4*)(CV + (size_t)pair * WIN * D_HEAD);

    float4 acc0, acc1, acc2, acc3;
    acc0.x=acc0.y=acc0.z=acc0.w=0.f; acc1=acc0; acc2=acc0; acc3=acc0;
    float lsum = 0.f;
    const float scale = 0.08838834764831845f;   // 1/sqrt(128)

    int base = lo + 2 * w;
    if (base < hi) {
        const float4* kp = Kb + (size_t)base * 32 + lane;
        const float4* vp = Vb + (size_t)base * 32 + lane;
        int ob = (base + 1 < hi) ? 32 : 0;
        float4 ka = __ldcs(kp),       va = __ldcs(vp);
        float4 kb4 = __ldcs(kp + ob), vb4 = __ldcs(vp + ob);
        while (true) {
            const bool more = (base + 16) < hi;
            float4 kna, vna, knb, vnb;
            if (more) {
                int o2 = (base + 17 < hi) ? 544 : 512;
                kna = __ldcs(kp + 512); vna = __ldcs(vp + 512);
                knb = __ldcs(kp + o2);  vnb = __ldcs(vp + o2);
            }

            float a0 = q0.x*ka.x + q0.y*ka.y + q0.z*ka.z + q0.w*ka.w;
            float a1 = q1.x*ka.x + q1.y*ka.y + q1.z*ka.z + q1.w*ka.w;
            float a2 = q2.x*ka.x + q2.y*ka.y + q2.z*ka.z + q2.w*ka.w;
            float a3 = q3.x*ka.x + q3.y*ka.y + q3.z*ka.z + q3.w*ka.w;
            float b0 = q0.x*kb4.x + q0.y*kb4.y + q0.z*kb4.z + q0.w*kb4.w;
            float b1 = q1.x*kb4.x + q1.y*kb4.y + q1.z*kb4.z + q1.w*kb4.w;
            float b2 = q2.x*kb4.x + q2.y*kb4.y + q2.z*kb4.z + q2.w*kb4.w;
            float b3 = q3.x*kb4.x + q3.y*kb4.y + q3.z*kb4.z + q3.w*kb4.w;
            a0 += __shfl_xor_sync(0xffffffffu, a0, 1);
            a1 += __shfl_xor_sync(0xffffffffu, a1, 1);
            a2 += __shfl_xor_sync(0xffffffffu, a2, 1);
            a3 += __shfl_xor_sync(0xffffffffu, a3, 1);
            b0 += __shfl_xor_sync(0xffffffffu, b0, 1);
            b1 += __shfl_xor_sync(0xffffffffu, b1, 1);
            b2 += __shfl_xor_sync(0xffffffffu, b2, 1);
            b3 += __shfl_xor_sync(0xffffffffu, b3, 1);
            a0 += __shfl_xor_sync(0xffffffffu, a0, 2);
            a1 += __shfl_xor_sync(0xffffffffu, a1, 2);
            a2 += __shfl_xor_sync(0xffffffffu, a2, 2);
            a3 += __shfl_xor_sync(0xffffffffu, a3, 2);
            b0 += __shfl_xor_sync(0xffffffffu, b0, 2);
            b1 += __shfl_xor_sync(0xffffffffu, b1, 2);
            b2 += __shfl_xor_sync(0xffffffffu, b2, 2);
            b3 += __shfl_xor_sync(0xffffffffu, b3, 2);
            float tA = g1 ? a1 : a0;
            float tB = g1 ? a3 : a2;
            float sa = g2 ? tB : tA;
            float uA = g1 ? b1 : b0;
            float uB = g1 ? b3 : b2;
            float sb = g2 ? uB : uA;
            sa += __shfl_xor_sync(0xffffffffu, sa, 4);
            sb += __shfl_xor_sync(0xffffffffu, sb, 4);
            sa += __shfl_xor_sync(0xffffffffu, sa, 8);
            sb += __shfl_xor_sync(0xffffffffu, sb, 8);
            sa += __shfl_xor_sync(0xffffffffu, sa, 16);
            sb += __shfl_xor_sync(0xffffffffu, sb, 16);
            float pa = __expf(sa * scale);
            float pb = (base + 1 < hi) ? __expf(sb * scale) : 0.f;
            lsum += pa + pb;
            float pa0 = __shfl_sync(0xffffffffu, pa, 0, 4);
            float pa1 = __shfl_sync(0xffffffffu, pa, 1, 4);
            float pa2 = __shfl_sync(0xffffffffu, pa, 2, 4);
            float pa3 = __shfl_sync(0xffffffffu, pa, 3, 4);
            float pb0 = __shfl_sync(0xffffffffu, pb, 0, 4);
            float pb1 = __shfl_sync(0xffffffffu, pb, 1, 4);
            float pb2 = __shfl_sync(0xffffffffu, pb, 2, 4);
            float pb3 = __shfl_sync(0xffffffffu, pb, 3, 4);
            acc0.x += pa0*va.x + pb0*vb4.x;  acc0.y += pa0*va.y + pb0*vb4.y;
            acc0.z += pa0*va.z + pb0*vb4.z;  acc0.w += pa0*va.w + pb0*vb4.w;
            acc1.x += pa1*va.x + pb1*vb4.x;  acc1.y += pa1*va.y + pb1*vb4.y;
            acc1.z += pa1*va.z + pb1*vb4.z;  acc1.w += pa1*va.w + pb1*vb4.w;
            acc2.x += pa2*va.x + pb2*vb4.x;  acc2.y += pa2*va.y + pb2*vb4.y;
            acc2.z += pa2*va.z + pb2*vb4.z;  acc2.w += pa2*va.w + pb2*vb4.w;
            acc3.x += pa3*va.x + pb3*vb4.x;  acc3.y += pa3*va.y + pb3*vb4.y;
            acc3.z += pa3*va.z + pb3*vb4.z;  acc3.w += pa3*va.w + pb3*vb4.w;

            if (!more) break;
            base += 16; kp += 512; vp += 512;
            ka = kna; va = vna; kb4 = knb; vb4 = vnb;
        }
    }

    __shared__ float4 sA4[8][GQ][32];
    __shared__ float  sL[8][GQ];
    sA4[w][0][lane] = acc0;
    sA4[w][1][lane] = acc1;
    sA4[w][2][lane] = acc2;
    sA4[w][3][lane] = acc3;
    if (lane < 4) sL[w][lane] = lsum;
    __syncthreads();

    const int obase = (pair * NSPLIT + split) * GQ;
    {
        const int half = tid >> 7;
        const int d    = tid & 127;
#pragma unroll
        for (int g = half; g < GQ; g += 2) {
            float A = 0.f;
#pragma unroll
            for (int ww = 0; ww < 8; ++ww)
                A += ((const float*)&sA4[ww][g][0])[d];
            g_pa[(obase + g) * D_HEAD + d] = A;
        }
        if (tid < 4) {
            float z = 0.f;
#pragma unroll
            for (int ww = 0; ww < 8; ++ww) z += sL[ww][tid];
            g_pl[obase + tid] = z;
        }
    }
}

// ---------------- 4) combine splits + new-token row -> ctx ---------------
// One warp per (pair, group); lanes = float4 d-chunks, 16 unrolled loads.
__global__ void __launch_bounds__(256) k_attn_red() {
    const int W    = blockIdx.x * 8 + (threadIdx.x >> 5);   // (pair, g)
    const int lane = threadIdx.x & 31;
    const int pair = W >> 2, g = W & 3;
    const int b = pair >> 3, kv = pair & 7;

    float4 qv = *(const float4*)&g_q[((b * HQ) + kv * GQ + g) * D_HEAD + 4 * lane];
    float4 kn = *(const float4*)&g_k[pair * D_HEAD + 4 * lane];
    float s = qv.x*kn.x + qv.y*kn.y + qv.z*kn.z + qv.w*kn.w;
#pragma unroll
    for (int off = 16; off > 0; off >>= 1)
        s += __shfl_xor_sync(0xffffffffu, s, off);
    const float p = __expf(s * 0.08838834764831845f);

    float4 vn = *(const float4*)&g_v[pair * D_HEAD + 4 * lane];
    float Z = p;
    float4 A = make_float4(p * vn.x, p * vn.y, p * vn.z, p * vn.w);
#pragma unroll
    for (int sp = 0; sp < NSPLIT; ++sp) {
        int idx = (pair * NSPLIT + sp) * GQ + g;
        Z += g_pl[idx];
        float4 t = *(const float4*)&g_pa[idx * D_HEAD + 4 * lane];
        A.x += t.x; A.y += t.y; A.z += t.z; A.w += t.w;
    }
    const float inv = 1.f / Z;
    const int c = (kv * GQ + g) * D_HEAD + 4 * lane;
    *(float4*)&g_ctx[b * HID + c] = make_float4(A.x*inv, A.y*inv, A.z*inv, A.w*inv);
}

// ---------------- 5) sum wo K-split partials into the output (float4) -----
__global__ void k_addout(float* __restrict__ out) {
    int i = blockIdx.x * blockDim.x + threadIdx.x;   // BATCH*HID/4 threads
    float4 s = make_float4(0.f, 0.f, 0.f, 0.f);
#pragma unroll
    for (int k = 0; k < KS; ++k) {
        float4 t = *(const float4*)&g_op[k * BATCH * HID + 4 * i];
        s.x += t.x; s.y += t.y; s.z += t.z; s.w += t.w;
    }
    *(float4*)&out[4 * i] = s;
}

// ---------------- launch ----------------
extern "C" void kernel_launch(void* const* d_in, const int* in_sizes, int n_in,
                              void* d_out, int out_size) {
    const float* x    = (const float*)d_in[0];
    const float* wqkv = (const float*)d_in[1];
    const float* wo   = (const float*)d_in[2];
    const float* ck   = (const float*)d_in[3];
    const float* cv   = (const float*)d_in[4];
    const float* cosc = (const float*)d_in[5];
    const float* sinc = (const float*)d_in[6];
    // d_in[7] = attn_mask: equivalent to (pos <= start_pos), applied analytically
    const int* sp = (const int*)d_in[8];
    // d_in[9] = current_pos (== start_pos; new-token row handled in k_attn_red)
    float* out = (float*)d_out;

    static bool attr_set = false;
    if (!attr_set) {
        cudaFuncSetAttribute(k_gemm_tc,
                             cudaFuncAttributeMaxDynamicSharedMemorySize,
                             SMEM_GEMM);
        attr_set = true;
    }

    float* ctx; float* xp; float* op;
    cudaGetSymbolAddress((void**)&ctx, g_ctx);
    cudaGetSymbolAddress((void**)&xp,  g_xp);
    cudaGetSymbolAddress((void**)&op,  g_op);

    dim3 gq(QKV_COLS / 64, KS);
    k_gemm_tc<<<gq, 256, SMEM_GEMM>>>(x, wqkv, xp, QKV_COLS);
    k_rope<<<RPE_TOT / 256, 256>>>(cosc, sinc, sp);
    dim3 ag(NSPLIT, PAIRS);
    k_attn_part<<<ag, 256>>>(ck, cv, sp);
    k_attn_red<<<(PAIRS * GQ) / 8, 256>>>();
    dim3 go(HID / 64, KS);
    k_gemm_tc<<<go, 256, SMEM_GEMM>>>(ctx, wo, op, HID);
    k_addout<<<(BATCH * HID) / 1024, 256>>>(out);
}

// round 14
// speedup vs baseline: 1.0375x; 1.0337x over previous
#include <cuda_runtime.h>
#include <math.h>
#include <stdint.h>

// ---------------- problem constants ----------------
#define BATCH 32
#define HQ    32
#define KVH   8
#define GQ    4           // HQ / KVH
#define D_HEAD 128
#define HID   4096
#define QKV_COLS 6144     // (H + 2*KVH) * D_HEAD
#define WIN   4096
#define NSPLIT 8
#define PAIRS (BATCH*KVH) // 256
#define KS_QKV 8          // K-split for the qkv GEMM (384 CTAs, 16 tiles)
#define KS_WO  16         // K-split for the wo  GEMM (512 CTAs,  8 tiles)

// ---------------- device scratch (no allocations allowed) ----------------
__device__ float g_ctx[BATCH * HID];                // attention output [b][h*128+d]
__device__ float g_xp [KS_QKV * BATCH * QKV_COLS];  // qkv gemm partials
__device__ float g_op [KS_WO  * BATCH * HID];       // wo  gemm partials
__device__ float g_q  [BATCH * HQ  * D_HEAD];       // rope'd q  [b][h][d]
__device__ float g_k  [BATCH * KVH * D_HEAD];       // rope'd new k [b][kv][d]
__device__ float g_v  [BATCH * KVH * D_HEAD];       // new v
__device__ float g_pl [PAIRS * NSPLIT * GQ];
__device__ float g_pa [PAIRS * NSPLIT * GQ * D_HEAD];

// ---------------- PTX helpers ----------------
__device__ __forceinline__ uint32_t f2tf32(float f) {
    uint32_t r;
    asm("cvt.rna.tf32.f32 %0, %1;" : "=r"(r) : "f"(f));
    return r;
}
__device__ __forceinline__ void mma_tf32(float& c0, float& c1, float& c2, float& c3,
                                         uint32_t a0, uint32_t a1, uint32_t a2, uint32_t a3,
                                         uint32_t b0, uint32_t b1) {
    asm("mma.sync.aligned.m16n8k8.row.col.f32.tf32.tf32.f32 "
        "{%0,%1,%2,%3},{%4,%5,%6,%7},{%8,%9},{%0,%1,%2,%3};"
        : "+f"(c0), "+f"(c1), "+f"(c2), "+f"(c3)
        : "r"(a0), "r"(a1), "r"(a2), "r"(a3), "r"(b0), "r"(b1));
}
__device__ __forceinline__ void cp16(void* dst, const void* src) {
    uint32_t d = (uint32_t)__cvta_generic_to_shared(dst);
    asm volatile("cp.async.cg.shared.global [%0], [%1], 16;" :: "r"(d), "l"(src));
}
__device__ __forceinline__ void cp_commit() {
    asm volatile("cp.async.commit_group;" ::: "memory");
}
template <int N>
__device__ __forceinline__ void cp_wait() {
    asm volatile("cp.async.wait_group %0;" :: "n"(N) : "memory");
}

// ---------------- 1) tf32 tensor-core GEMM, 3-stage pipeline --------------
// Y_part[ks][32][NCOL] = A[32][32*ntiles] @ W[kseg][NCOL], kseg = 32*ntiles.
// CTA: 256 thr = 8 warps (2 m x 4 n), CTA tile 32 x 128, K-tile 32.
// ntiles is the per-CTA K depth: qkv uses 16 (KS=8), wo uses 8 (KS=16).
#define SMB_PITCH 136
#define SMA_PITCH 36
#define SMB_STG   (32 * SMB_PITCH)   // 4352
#define SMA_STG   (32 * SMA_PITCH)   // 1152
#define SMEM_GEMM ((3 * SMB_STG + 3 * SMA_STG) * 4)   // 66048 bytes

__global__ void __launch_bounds__(256, 3) k_gemm_tc(const float* __restrict__ A,
                                                    const float* __restrict__ W,
                                                    float* __restrict__ Yp,
                                                    int NCOL, int ntiles) {
    extern __shared__ float sm[];
    float* sB = sm;                      // [3][32][136]
    float* sA = sm + 3 * SMB_STG;        // [3][32][36]

    const int tid  = threadIdx.x, lane = tid & 31, w = tid >> 5;
    const int n0   = blockIdx.x * 128;
    const int kbase = blockIdx.y * (ntiles * 32);
    const int mw = w & 1, nw = w >> 1;
    const int gid = lane >> 2, tig = lane & 3;

    const int br = tid >> 5, bc4 = (tid & 31) << 2;
    const int ar = tid >> 3, aj  = (tid & 7) << 2;

#define LOAD_TILE(T, S)                                                        \
    {                                                                          \
        const int k0 = kbase + (T) * 32;                                       \
        const float* wsrc = W + (size_t)k0 * NCOL + n0;                        \
        float* bd = sB + (S) * SMB_STG;                                        \
        _Pragma("unroll")                                                      \
        for (int i = 0; i < 4; ++i)                                            \
            cp16(bd + (br + 8 * i) * SMB_PITCH + bc4,                          \
                 wsrc + (size_t)(br + 8 * i) * NCOL + bc4);                    \
        cp16(sA + (S) * SMA_STG + ar * SMA_PITCH + aj, A + ar * HID + k0 + aj);\
    }

    float c0[4], c1[4], c2[4], c3[4];
#pragma unroll
    for (int j = 0; j < 4; ++j) { c0[j] = c1[j] = c2[j] = c3[j] = 0.f; }

    LOAD_TILE(0, 0);
    cp_commit();
    LOAD_TILE(1, 1);
    cp_commit();

#pragma unroll 1
    for (int t = 0; t < ntiles; ++t) {
        if (t + 1 < ntiles) cp_wait<1>(); else cp_wait<0>();
        __syncthreads();
        if (t + 2 < ntiles) {
            LOAD_TILE(t + 2, (t + 2) % 3);
            cp_commit();
        }

        const int st = t % 3;
        const float* bb = sB + st * SMB_STG;
        const float* aa = sA + st * SMA_STG;

#pragma unroll
        for (int s8 = 0; s8 < 4; ++s8) {
            const int kc = 8 * s8;
            const int rA = (mw * 16 + gid) * SMA_PITCH + kc + tig;
            uint32_t A0 = f2tf32(aa[rA]);
            uint32_t A1 = f2tf32(aa[rA + 8 * SMA_PITCH]);
            uint32_t A2 = f2tf32(aa[rA + 4]);
            uint32_t A3 = f2tf32(aa[rA + 8 * SMA_PITCH + 4]);
#pragma unroll
            for (int j = 0; j < 4; ++j) {
                const int nn = nw * 32 + j * 8 + gid;
                uint32_t B0 = f2tf32(bb[(kc + tig) * SMB_PITCH + nn]);
                uint32_t B1 = f2tf32(bb[(kc + tig + 4) * SMB_PITCH + nn]);
                mma_tf32(c0[j], c1[j], c2[j], c3[j], A0, A1, A2, A3, B0, B1);
            }
        }
    }

    float* Y = Yp + (size_t)blockIdx.y * BATCH * NCOL;
    const int row = mw * 16 + gid;
#pragma unroll
    for (int j = 0; j < 4; ++j) {
        const int col = n0 + nw * 32 + j * 8 + 2 * tig;
        *(float2*)&Y[(size_t)row * NCOL + col]       = make_float2(c0[j], c1[j]);
        *(float2*)&Y[(size_t)(row + 8) * NCOL + col] = make_float2(c2[j], c3[j]);
    }
}

// ---------------- 2) RoPE: one thread per rotation pair -------------------
#define RPE_HEADS ((HQ + KVH) * 64)             // 2560 pair-slots per batch row
#define RPE_PAIRS (BATCH * RPE_HEADS)           // 81920
#define RPE_V     (BATCH * KVH * D_HEAD)        // 32768
#define RPE_TOT   (RPE_PAIRS + RPE_V)           // 114688

__device__ __forceinline__ float psum_x(int i) {
    float s = 0.f;
#pragma unroll
    for (int k = 0; k < KS_QKV; ++k) s += g_xp[k * BATCH * QKV_COLS + i];
    return s;
}
__global__ void k_rope(const float* __restrict__ cosc,
                       const float* __restrict__ sinc,
                       const int* __restrict__ sp_p) {
    int i = blockIdx.x * blockDim.x + threadIdx.x;   // RPE_TOT threads
    int sp = *sp_p;
    if (i < RPE_PAIRS) {
        int m = i / RPE_HEADS;
        int r = i - m * RPE_HEADS;        // h*64 + d
        int h = r >> 6, d = r & 63;
        int c = h * D_HEAD + d;
        float a  = psum_x(m * QKV_COLS + c);
        float bb = psum_x(m * QKV_COLS + c + 64);
        float cs0 = cosc[sp * D_HEAD + d],      sn0 = sinc[sp * D_HEAD + d];
        float cs1 = cosc[sp * D_HEAD + d + 64], sn1 = sinc[sp * D_HEAD + d + 64];
        float o0 = a * cs0 - bb * sn0;    // rot[d]    = -u[d+64]
        float o1 = bb * cs1 + a * sn1;    // rot[d+64] =  u[d]
        if (h < HQ) {
            g_q[m * (HQ * D_HEAD) + c]      = o0;
            g_q[m * (HQ * D_HEAD) + c + 64] = o1;
        } else {
            int cc = (h - HQ) * D_HEAD + d;
            g_k[m * (KVH * D_HEAD) + cc]      = o0;
            g_k[m * (KVH * D_HEAD) + cc + 64] = o1;
        }
    } else {
        int j = i - RPE_PAIRS;            // v element
        int m = j >> 10, cc = j & 1023;   // KVH*D_HEAD = 1024
        g_v[m * (KVH * D_HEAD) + cc] = psum_x(m * QKV_COLS + (HQ + KVH) * D_HEAD + cc);
    }
}

// ---------------- 3) flash-decode partials: 2 rows/iter, streaming loads --
__global__ void __launch_bounds__(256, 3) k_attn_part(const float* __restrict__ CK,
                                                      const float* __restrict__ CV,
                                                      const int* __restrict__ sp_p) {
    const int split = blockIdx.x;
    const int pair  = blockIdx.y;            // b*8 + kv
    const int b  = pair >> 3;
    const int kv = pair & 7;
    const int Lr = *sp_p;                    // 3000 cache rows
    const int rows = (Lr + NSPLIT - 1) / NSPLIT;
    const int lo = split * rows;
    const int hi = min(lo + rows, Lr);
    const int tid = threadIdx.x, lane = tid & 31, w = tid >> 5;
    const bool g1 = (lane & 1), g2 = (lane & 2);

    float4 q0 = *(const float4*)&g_q[((b * HQ) + kv * GQ + 0) * D_HEAD + 4 * lane];
    float4 q1 = *(const float4*)&g_q[((b * HQ) + kv * GQ + 1) * D_HEAD + 4 * lane];
    float4 q2 = *(const float4*)&g_q[((b * HQ) + kv * GQ + 2) * D_HEAD + 4 * lane];
    float4 q3 = *(const float4*)&g_q[((b * HQ) + kv * GQ + 3) * D_HEAD + 4 * lane];

    const float4* Kb = (const float4*)(CK + (size_t)pair * WIN * D_HEAD);
    const float4* Vb = (const float4*)(CV + (size_t)pair * WIN * D_HEAD);

    float4 acc0, acc1, acc2, acc3;
    acc0.x=acc0.y=acc0.z=acc0.w=0.f; acc1=acc0; acc2=acc0; acc3=acc0;
    float lsum = 0.f;
    const float scale = 0.08838834764831845f;   // 1/sqrt(128)

    int base = lo + 2 * w;
    if (base < hi) {
        const float4* kp = Kb + (size_t)base * 32 + lane;
        const float4* vp = Vb + (size_t)base * 32 + lane;
        int ob = (base + 1 < hi) ? 32 : 0;
        float4 ka = __ldcs(kp),       va = __ldcs(vp);
        float4 kb4 = __ldcs(kp + ob), vb4 = __ldcs(vp + ob);
        while (true) {
            const bool more = (base + 16) < hi;
            float4 kna, vna, knb, vnb;
            if (more) {
                int o2 = (base + 17 < hi) ? 544 : 512;
                kna = __ldcs(kp + 512); vna = __ldcs(vp + 512);
                knb = __ldcs(kp + o2);  vnb = __ldcs(vp + o2);
            }

            float a0 = q0.x*ka.x + q0.y*ka.y + q0.z*ka.z + q0.w*ka.w;
            float a1 = q1.x*ka.x + q1.y*ka.y + q1.z*ka.z + q1.w*ka.w;
            float a2 = q2.x*ka.x + q2.y*ka.y + q2.z*ka.z + q2.w*ka.w;
            float a3 = q3.x*ka.x + q3.y*ka.y + q3.z*ka.z + q3.w*ka.w;
            float b0 = q0.x*kb4.x + q0.y*kb4.y + q0.z*kb4.z + q0.w*kb4.w;
            float b1 = q1.x*kb4.x + q1.y*kb4.y + q1.z*kb4.z + q1.w*kb4.w;
            float b2 = q2.x*kb4.x + q2.y*kb4.y + q2.z*kb4.z + q2.w*kb4.w;
            float b3 = q3.x*kb4.x + q3.y*kb4.y + q3.z*kb4.z + q3.w*kb4.w;
            a0 += __shfl_xor_sync(0xffffffffu, a0, 1);
            a1 += __shfl_xor_sync(0xffffffffu, a1, 1);
            a2 += __shfl_xor_sync(0xffffffffu, a2, 1);
            a3 += __shfl_xor_sync(0xffffffffu, a3, 1);
            b0 += __shfl_xor_sync(0xffffffffu, b0, 1);
            b1 += __shfl_xor_sync(0xffffffffu, b1, 1);
            b2 += __shfl_xor_sync(0xffffffffu, b2, 1);
            b3 += __shfl_xor_sync(0xffffffffu, b3, 1);
            a0 += __shfl_xor_sync(0xffffffffu, a0, 2);
            a1 += __shfl_xor_sync(0xffffffffu, a1, 2);
            a2 += __shfl_xor_sync(0xffffffffu, a2, 2);
            a3 += __shfl_xor_sync(0xffffffffu, a3, 2);
            b0 += __shfl_xor_sync(0xffffffffu, b0, 2);
            b1 += __shfl_xor_sync(0xffffffffu, b1, 2);
            b2 += __shfl_xor_sync(0xffffffffu, b2, 2);
            b3 += __shfl_xor_sync(0xffffffffu, b3, 2);
            float tA = g1 ? a1 : a0;
            float tB = g1 ? a3 : a2;
            float sa = g2 ? tB : tA;
            float uA = g1 ? b1 : b0;
            float uB = g1 ? b3 : b2;
            float sb = g2 ? uB : uA;
            sa += __shfl_xor_sync(0xffffffffu, sa, 4);
            sb += __shfl_xor_sync(0xffffffffu, sb, 4);
            sa += __shfl_xor_sync(0xffffffffu, sa, 8);
            sb += __shfl_xor_sync(0xffffffffu, sb, 8);
            sa += __shfl_xor_sync(0xffffffffu, sa, 16);
            sb += __shfl_xor_sync(0xffffffffu, sb, 16);
            float pa = __expf(sa * scale);
            float pb = (base + 1 < hi) ? __expf(sb * scale) : 0.f;
            lsum += pa + pb;
            float pa0 = __shfl_sync(0xffffffffu, pa, 0, 4);
            float pa1 = __shfl_sync(0xffffffffu, pa, 1, 4);
            float pa2 = __shfl_sync(0xffffffffu, pa, 2, 4);
            float pa3 = __shfl_sync(0xffffffffu, pa, 3, 4);
            float pb0 = __shfl_sync(0xffffffffu, pb, 0, 4);
            float pb1 = __shfl_sync(0xffffffffu, pb, 1, 4);
            float pb2 = __shfl_sync(0xffffffffu, pb, 2, 4);
            float pb3 = __shfl_sync(0xffffffffu, pb, 3, 4);
            acc0.x += pa0*va.x + pb0*vb4.x;  acc0.y += pa0*va.y + pb0*vb4.y;
            acc0.z += pa0*va.z + pb0*vb4.z;  acc0.w += pa0*va.w + pb0*vb4.w;
            acc1.x += pa1*va.x + pb1*vb4.x;  acc1.y += pa1*va.y + pb1*vb4.y;
            acc1.z += pa1*va.z + pb1*vb4.z;  acc1.w += pa1*va.w + pb1*vb4.w;
            acc2.x += pa2*va.x + pb2*vb4.x;  acc2.y += pa2*va.y + pb2*vb4.y;
            acc2.z += pa2*va.z + pb2*vb4.z;  acc2.w += pa2*va.w + pb2*vb4.w;
            acc3.x += pa3*va.x + pb3*vb4.x;  acc3.y += pa3*va.y + pb3*vb4.y;
            acc3.z += pa3*va.z + pb3*vb4.z;  acc3.w += pa3*va.w + pb3*vb4.w;

            if (!more) break;
            base += 16; kp += 512; vp += 512;
            ka = kna; va = vna; kb4 = knb; vb4 = vnb;
        }
    }

    __shared__ float4 sA4[8][GQ][32];
    __shared__ float  sL[8][GQ];
    sA4[w][0][lane] = acc0;
    sA4[w][1][lane] = acc1;
    sA4[w][2][lane] = acc2;
    sA4[w][3][lane] = acc3;
    if (lane < 4) sL[w][lane] = lsum;
    __syncthreads();

    const int obase = (pair * NSPLIT + split) * GQ;
    {
        const int half = tid >> 7;
        const int d    = tid & 127;
#pragma unroll
        for (int g = half; g < GQ; g += 2) {
            float A = 0.f;
#pragma unroll
            for (int ww = 0; ww < 8; ++ww)
                A += ((const float*)&sA4[ww][g][0])[d];
            g_pa[(obase + g) * D_HEAD + d] = A;
        }
        if (tid < 4) {
            float z = 0.f;
#pragma unroll
            for (int ww = 0; ww < 8; ++ww) z += sL[ww][tid];
            g_pl[obase + tid] = z;
        }
    }
}

// ---------------- 4) combine splits + new-token row -> ctx ---------------
// One warp per (pair, group); lanes = float4 d-chunks, NSPLIT unrolled loads.
__global__ void __launch_bounds__(256) k_attn_red() {
    const int W    = blockIdx.x * 8 + (threadIdx.x >> 5);   // (pair, g)
    const int lane = threadIdx.x & 31;
    const int pair = W >> 2, g = W & 3;
    const int b = pair >> 3, kv = pair & 7;

    float4 qv = *(const float4*)&g_q[((b * HQ) + kv * GQ + g) * D_HEAD + 4 * lane];
    float4 kn = *(const float4*)&g_k[pair * D_HEAD + 4 * lane];
    float s = qv.x*kn.x + qv.y*kn.y + qv.z*kn.z + qv.w*kn.w;
#pragma unroll
    for (int off = 16; off > 0; off >>= 1)
        s += __shfl_xor_sync(0xffffffffu, s, off);
    const float p = __expf(s * 0.08838834764831845f);

    float4 vn = *(const float4*)&g_v[pair * D_HEAD + 4 * lane];
    float Z = p;
    float4 A = make_float4(p * vn.x, p * vn.y, p * vn.z, p * vn.w);
#pragma unroll
    for (int sp = 0; sp < NSPLIT; ++sp) {
        int idx = (pair * NSPLIT + sp) * GQ + g;
        Z += g_pl[idx];
        float4 t = *(const float4*)&g_pa[idx * D_HEAD + 4 * lane];
        A.x += t.x; A.y += t.y; A.z += t.z; A.w += t.w;
    }
    const float inv = 1.f / Z;
    const int c = (kv * GQ + g) * D_HEAD + 4 * lane;
    *(float4*)&g_ctx[b * HID + c] = make_float4(A.x*inv, A.y*inv, A.z*inv, A.w*inv);
}

// ---------------- 5) sum wo K-split partials into the output (float4) -----
__global__ void k_addout(float* __restrict__ out) {
    int i = blockIdx.x * blockDim.x + threadIdx.x;   // BATCH*HID/4 threads
    float4 s = make_float4(0.f, 0.f, 0.f, 0.f);
#pragma unroll
    for (int k = 0; k < KS_WO; ++k) {
        float4 t = *(const float4*)&g_op[k * BATCH * HID + 4 * i];
        s.x += t.x; s.y += t.y; s.z += t.z; s.w += t.w;
    }
    *(float4*)&out[4 * i] = s;
}

// ---------------- launch ----------------
extern "C" void kernel_launch(void* const* d_in, const int* in_sizes, int n_in,
                              void* d_out, int out_size) {
    const float* x    = (const float*)d_in[0];
    const float* wqkv = (const float*)d_in[1];
    const float* wo   = (const float*)d_in[2];
    const float* ck   = (const float*)d_in[3];
    const float* cv   = (const float*)d_in[4];
    const float* cosc = (const float*)d_in[5];
    const float* sinc = (const float*)d_in[6];
    // d_in[7] = attn_mask: equivalent to (pos <= start_pos), applied analytically
    const int* sp = (const int*)d_in[8];
    // d_in[9] = current_pos (== start_pos; new-token row handled in k_attn_red)
    float* out = (float*)d_out;

    static bool attr_set = false;
    if (!attr_set) {
        cudaFuncSetAttribute(k_gemm_tc,
                             cudaFuncAttributeMaxDynamicSharedMemorySize,
                             SMEM_GEMM);
        attr_set = true;
    }

    float* ctx; float* xp; float* op;
    cudaGetSymbolAddress((void**)&ctx, g_ctx);
    cudaGetSymbolAddress((void**)&xp,  g_xp);
    cudaGetSymbolAddress((void**)&op,  g_op);

    dim3 gq(QKV_COLS / 128, KS_QKV);
    k_gemm_tc<<<gq, 256, SMEM_GEMM>>>(x, wqkv, xp, QKV_COLS, HID / (32 * KS_QKV));
    k_rope<<<RPE_TOT / 256, 256>>>(cosc, sinc, sp);
    dim3 ag(NSPLIT, PAIRS);
    k_attn_part<<<ag, 256>>>(ck, cv, sp);
    k_attn_red<<<(PAIRS * GQ) / 8, 256>>>();
    dim3 go(HID / 128, KS_WO);
    k_gemm_tc<<<go, 256, SMEM_GEMM>>>(ctx, wo, op, HID, HID / (32 * KS_WO));
    k_addout<<<(BATCH * HID) / 1024, 256>>>(out);
}

// round 15
// speedup vs baseline: 1.0533x; 1.0152x over previous
#include <cuda_runtime.h>
#include <math.h>
#include <stdint.h>

// ---------------- problem constants ----------------
#define BATCH 32
#define HQ    32
#define KVH   8
#define GQ    4           // HQ / KVH
#define D_HEAD 128
#define HID   4096
#define QKV_COLS 6144     // (H + 2*KVH) * D_HEAD
#define WIN   4096
#define NSPLIT 8
#define PAIRS (BATCH*KVH) // 256
#define KS    8           // GEMM K-split (both GEMMs)
#define TKTILES (HID / (32 * KS))   // 16 k-tiles of 32 per CTA

// ---------------- device scratch (no allocations allowed) ----------------
__device__ float g_ctx[BATCH * HID];            // attention output [b][h*128+d]
__device__ float g_xp [KS * BATCH * QKV_COLS];  // qkv gemm partials
__device__ float g_op [KS * BATCH * HID];       // wo  gemm partials
__device__ float g_q  [BATCH * HQ  * D_HEAD];   // rope'd q  [b][h][d]
__device__ float g_k  [BATCH * KVH * D_HEAD];   // rope'd new k [b][kv][d]
__device__ float g_v  [BATCH * KVH * D_HEAD];   // new v
__device__ float g_pl [PAIRS * NSPLIT * GQ];
__device__ float g_pa [PAIRS * NSPLIT * GQ * D_HEAD];

// ---------------- PTX helpers ----------------
__device__ __forceinline__ uint32_t f2tf32(float f) {
    uint32_t r;
    asm("cvt.rna.tf32.f32 %0, %1;" : "=r"(r) : "f"(f));
    return r;
}
__device__ __forceinline__ void mma_tf32(float& c0, float& c1, float& c2, float& c3,
                                         uint32_t a0, uint32_t a1, uint32_t a2, uint32_t a3,
                                         uint32_t b0, uint32_t b1) {
    asm("mma.sync.aligned.m16n8k8.row.col.f32.tf32.tf32.f32 "
        "{%0,%1,%2,%3},{%4,%5,%6,%7},{%8,%9},{%0,%1,%2,%3};"
        : "+f"(c0), "+f"(c1), "+f"(c2), "+f"(c3)
        : "r"(a0), "r"(a1), "r"(a2), "r"(a3), "r"(b0), "r"(b1));
}
__device__ __forceinline__ void cp16(void* dst, const void* src) {
    uint32_t d = (uint32_t)__cvta_generic_to_shared(dst);
    asm volatile("cp.async.cg.shared.global [%0], [%1], 16;" :: "r"(d), "l"(src));
}
__device__ __forceinline__ void cp_commit() {
    asm volatile("cp.async.commit_group;" ::: "memory");
}
template <int N>
__device__ __forceinline__ void cp_wait() {
    asm volatile("cp.async.wait_group %0;" :: "n"(N) : "memory");
}

// ---------------- 1) tf32 tensor-core GEMM, 2-stage pipeline, 4 CTAs/SM ---
// Y_part[ks][32][NCOL] = A[32][512] @ W[kseg][NCOL].
// CTA: 256 thr = 8 warps (2 m x 4 n), CTA tile 32 x 128, K-tile 32.
// 2 smem stages (44 KB) so 4 CTAs/SM fit; inner loop identical to the
// validated 3-stage version (R8-R10) — only pipeline depth/occupancy change.
#define SMB_PITCH 136
#define SMA_PITCH 36
#define SMB_STG   (32 * SMB_PITCH)   // 4352
#define SMA_STG   (32 * SMA_PITCH)   // 1152
#define SMEM_GEMM ((2 * SMB_STG + 2 * SMA_STG) * 4)   // 44032 bytes

__global__ void __launch_bounds__(256, 4) k_gemm_tc(const float* __restrict__ A,
                                                    const float* __restrict__ W,
                                                    float* __restrict__ Yp,
                                                    int NCOL) {
    extern __shared__ float sm[];
    float* sB = sm;                      // [2][32][136]
    float* sA = sm + 2 * SMB_STG;        // [2][32][36]

    const int tid  = threadIdx.x, lane = tid & 31, w = tid >> 5;
    const int n0   = blockIdx.x * 128;
    const int kbase = blockIdx.y * (TKTILES * 32);
    const int mw = w & 1, nw = w >> 1;
    const int gid = lane >> 2, tig = lane & 3;

    const int br = tid >> 5, bc4 = (tid & 31) << 2;
    const int ar = tid >> 3, aj  = (tid & 7) << 2;

#define LOAD_TILE(T, S)                                                        \
    {                                                                          \
        const int k0 = kbase + (T) * 32;                                       \
        const float* wsrc = W + (size_t)k0 * NCOL + n0;                        \
        float* bd = sB + (S) * SMB_STG;                                        \
        _Pragma("unroll")                                                      \
        for (int i = 0; i < 4; ++i)                                            \
            cp16(bd + (br + 8 * i) * SMB_PITCH + bc4,                          \
                 wsrc + (size_t)(br + 8 * i) * NCOL + bc4);                    \
        cp16(sA + (S) * SMA_STG + ar * SMA_PITCH + aj, A + ar * HID + k0 + aj);\
    }

    float c0[4], c1[4], c2[4], c3[4];
#pragma unroll
    for (int j = 0; j < 4; ++j) { c0[j] = c1[j] = c2[j] = c3[j] = 0.f; }

    LOAD_TILE(0, 0);
    cp_commit();

#pragma unroll 1
    for (int t = 0; t < TKTILES; ++t) {
        if (t + 1 < TKTILES) {
            LOAD_TILE(t + 1, (t + 1) & 1);   // stage freed by last iter's end-sync
            cp_commit();
            cp_wait<1>();
        } else {
            cp_wait<0>();
        }
        __syncthreads();

        const int st = t & 1;
        const float* bb = sB + st * SMB_STG;
        const float* aa = sA + st * SMA_STG;

#pragma unroll
        for (int s8 = 0; s8 < 4; ++s8) {
            const int kc = 8 * s8;
            const int rA = (mw * 16 + gid) * SMA_PITCH + kc + tig;
            uint32_t A0 = f2tf32(aa[rA]);
            uint32_t A1 = f2tf32(aa[rA + 8 * SMA_PITCH]);
            uint32_t A2 = f2tf32(aa[rA + 4]);
            uint32_t A3 = f2tf32(aa[rA + 8 * SMA_PITCH + 4]);
#pragma unroll
            for (int j = 0; j < 4; ++j) {
                const int nn = nw * 32 + j * 8 + gid;
                uint32_t B0 = f2tf32(bb[(kc + tig) * SMB_PITCH + nn]);
                uint32_t B1 = f2tf32(bb[(kc + tig + 4) * SMB_PITCH + nn]);
                mma_tf32(c0[j], c1[j], c2[j], c3[j], A0, A1, A2, A3, B0, B1);
            }
        }
        __syncthreads();   // all warps done with stage st before it is reloaded
    }

    float* Y = Yp + (size_t)blockIdx.y * BATCH * NCOL;
    const int row = mw * 16 + gid;
#pragma unroll
    for (int j = 0; j < 4; ++j) {
        const int col = n0 + nw * 32 + j * 8 + 2 * tig;
        *(float2*)&Y[(size_t)row * NCOL + col]       = make_float2(c0[j], c1[j]);
        *(float2*)&Y[(size_t)(row + 8) * NCOL + col] = make_float2(c2[j], c3[j]);
    }
}

// ---------------- 2) RoPE: one thread per rotation pair -------------------
#define RPE_HEADS ((HQ + KVH) * 64)             // 2560 pair-slots per batch row
#define RPE_PAIRS (BATCH * RPE_HEADS)           // 81920
#define RPE_V     (BATCH * KVH * D_HEAD)        // 32768
#define RPE_TOT   (RPE_PAIRS + RPE_V)           // 114688

__device__ __forceinline__ float psum_x(int i) {
    float s = 0.f;
#pragma unroll
    for (int k = 0; k < KS; ++k) s += g_xp[k * BATCH * QKV_COLS + i];
    return s;
}
__global__ void k_rope(const float* __restrict__ cosc,
                       const float* __restrict__ sinc,
                       const int* __restrict__ sp_p) {
    int i = blockIdx.x * blockDim.x + threadIdx.x;   // RPE_TOT threads
    int sp = *sp_p;
    if (i < RPE_PAIRS) {
        int m = i / RPE_HEADS;
        int r = i - m * RPE_HEADS;        // h*64 + d
        int h = r >> 6, d = r & 63;
        int c = h * D_HEAD + d;
        float a  = psum_x(m * QKV_COLS + c);
        float bb = psum_x(m * QKV_COLS + c + 64);
        float cs0 = cosc[sp * D_HEAD + d],      sn0 = sinc[sp * D_HEAD + d];
        float cs1 = cosc[sp * D_HEAD + d + 64], sn1 = sinc[sp * D_HEAD + d + 64];
        float o0 = a * cs0 - bb * sn0;    // rot[d]    = -u[d+64]
        float o1 = bb * cs1 + a * sn1;    // rot[d+64] =  u[d]
        if (h < HQ) {
            g_q[m * (HQ * D_HEAD) + c]      = o0;
            g_q[m * (HQ * D_HEAD) + c + 64] = o1;
        } else {
            int cc = (h - HQ) * D_HEAD + d;
            g_k[m * (KVH * D_HEAD) + cc]      = o0;
            g_k[m * (KVH * D_HEAD) + cc + 64] = o1;
        }
    } else {
        int j = i - RPE_PAIRS;            // v element
        int m = j >> 10, cc = j & 1023;   // KVH*D_HEAD = 1024
        g_v[m * (KVH * D_HEAD) + cc] = psum_x(m * QKV_COLS + (HQ + KVH) * D_HEAD + cc);
    }
}

// ---------------- 3) flash-decode partials: 2 rows/iter, streaming loads --
__global__ void __launch_bounds__(256, 3) k_attn_part(const float* __restrict__ CK,
                                                      const float* __restrict__ CV,
                                                      const int* __restrict__ sp_p) {
    const int split = blockIdx.x;
    const int pair  = blockIdx.y;            // b*8 + kv
    const int b  = pair >> 3;
    const int kv = pair & 7;
    const int Lr = *sp_p;                    // 3000 cache rows
    const int rows = (Lr + NSPLIT - 1) / NSPLIT;
    const int lo = split * rows;
    const int hi = min(lo + rows, Lr);
    const int tid = threadIdx.x, lane = tid & 31, w = tid >> 5;
    const bool g1 = (lane & 1), g2 = (lane & 2);

    float4 q0 = *(const float4*)&g_q[((b * HQ) + kv * GQ + 0) * D_HEAD + 4 * lane];
    float4 q1 = *(const float4*)&g_q[((b * HQ) + kv * GQ + 1) * D_HEAD + 4 * lane];
    float4 q2 = *(const float4*)&g_q[((b * HQ) + kv * GQ + 2) * D_HEAD + 4 * lane];
    float4 q3 = *(const float4*)&g_q[((b * HQ) + kv * GQ + 3) * D_HEAD + 4 * lane];

    const float4* Kb = (const float4*)(CK + (size_t)pair * WIN * D_HEAD);
    const float4* Vb = (const float4*)(CV + (size_t)pair * WIN * D_HEAD);

    float4 acc0, acc1, acc2, acc3;
    acc0.x=acc0.y=acc0.z=acc0.w=0.f; acc1=acc0; acc2=acc0; acc3=acc0;
    float lsum = 0.f;
    const float scale = 0.08838834764831845f;   // 1/sqrt(128)

    int base = lo + 2 * w;
    if (base < hi) {
        const float4* kp = Kb + (size_t)base * 32 + lane;
        const float4* vp = Vb + (size_t)base * 32 + lane;
        int ob = (base + 1 < hi) ? 32 : 0;
        float4 ka = __ldcs(kp),       va = __ldcs(vp);
        float4 kb4 = __ldcs(kp + ob), vb4 = __ldcs(vp + ob);
        while (true) {
            const bool more = (base + 16) < hi;
            float4 kna, vna, knb, vnb;
            if (more) {
                int o2 = (base + 17 < hi) ? 544 : 512;
                kna = __ldcs(kp + 512); vna = __ldcs(vp + 512);
                knb = __ldcs(kp + o2);  vnb = __ldcs(vp + o2);
            }

            float a0 = q0.x*ka.x + q0.y*ka.y + q0.z*ka.z + q0.w*ka.w;
            float a1 = q1.x*ka.x + q1.y*ka.y + q1.z*ka.z + q1.w*ka.w;
            float a2 = q2.x*ka.x + q2.y*ka.y + q2.z*ka.z + q2.w*ka.w;
            float a3 = q3.x*ka.x + q3.y*ka.y + q3.z*ka.z + q3.w*ka.w;
            float b0 = q0.x*kb4.x + q0.y*kb4.y + q0.z*kb4.z + q0.w*kb4.w;
            float b1 = q1.x*kb4.x + q1.y*kb4.y + q1.z*kb4.z + q1.w*kb4.w;
            float b2 = q2.x*kb4.x + q2.y*kb4.y + q2.z*kb4.z + q2.w*kb4.w;
            float b3 = q3.x*kb4.x + q3.y*kb4.y + q3.z*kb4.z + q3.w*kb4.w;
            a0 += __shfl_xor_sync(0xffffffffu, a0, 1);
            a1 += __shfl_xor_sync(0xffffffffu, a1, 1);
            a2 += __shfl_xor_sync(0xffffffffu, a2, 1);
            a3 += __shfl_xor_sync(0xffffffffu, a3, 1);
            b0 += __shfl_xor_sync(0xffffffffu, b0, 1);
            b1 += __shfl_xor_sync(0xffffffffu, b1, 1);
            b2 += __shfl_xor_sync(0xffffffffu, b2, 1);
            b3 += __shfl_xor_sync(0xffffffffu, b3, 1);
            a0 += __shfl_xor_sync(0xffffffffu, a0, 2);
            a1 += __shfl_xor_sync(0xffffffffu, a1, 2);
            a2 += __shfl_xor_sync(0xffffffffu, a2, 2);
            a3 += __shfl_xor_sync(0xffffffffu, a3, 2);
            b0 += __shfl_xor_sync(0xffffffffu, b0, 2);
            b1 += __shfl_xor_sync(0xffffffffu, b1, 2);
            b2 += __shfl_xor_sync(0xffffffffu, b2, 2);
            b3 += __shfl_xor_sync(0xffffffffu, b3, 2);
            float tA = g1 ? a1 : a0;
            float tB = g1 ? a3 : a2;
            float sa = g2 ? tB : tA;
            float uA = g1 ? b1 : b0;
            float uB = g1 ? b3 : b2;
            float sb = g2 ? uB : uA;
            sa += __shfl_xor_sync(0xffffffffu, sa, 4);
            sb += __shfl_xor_sync(0xffffffffu, sb, 4);
            sa += __shfl_xor_sync(0xffffffffu, sa, 8);
            sb += __shfl_xor_sync(0xffffffffu, sb, 8);
            sa += __shfl_xor_sync(0xffffffffu, sa, 16);
            sb += __shfl_xor_sync(0xffffffffu, sb, 16);
            float pa = __expf(sa * scale);
            float pb = (base + 1 < hi) ? __expf(sb * scale) : 0.f;
            lsum += pa + pb;
            float pa0 = __shfl_sync(0xffffffffu, pa, 0, 4);
            float pa1 = __shfl_sync(0xffffffffu, pa, 1, 4);
            float pa2 = __shfl_sync(0xffffffffu, pa, 2, 4);
            float pa3 = __shfl_sync(0xffffffffu, pa, 3, 4);
            float pb0 = __shfl_sync(0xffffffffu, pb, 0, 4);
            float pb1 = __shfl_sync(0xffffffffu, pb, 1, 4);
            float pb2 = __shfl_sync(0xffffffffu, pb, 2, 4);
            float pb3 = __shfl_sync(0xffffffffu, pb, 3, 4);
            acc0.x += pa0*va.x + pb0*vb4.x;  acc0.y += pa0*va.y + pb0*vb4.y;
            acc0.z += pa0*va.z + pb0*vb4.z;  acc0.w += pa0*va.w + pb0*vb4.w;
            acc1.x += pa1*va.x + pb1*vb4.x;  acc1.y += pa1*va.y + pb1*vb4.y;
            acc1.z += pa1*va.z + pb1*vb4.z;  acc1.w += pa1*va.w + pb1*vb4.w;
            acc2.x += pa2*va.x + pb2*vb4.x;  acc2.y += pa2*va.y + pb2*vb4.y;
            acc2.z += pa2*va.z + pb2*vb4.z;  acc2.w += pa2*va.w + pb2*vb4.w;
            acc3.x += pa3*va.x + pb3*vb4.x;  acc3.y += pa3*va.y + pb3*vb4.y;
            acc3.z += pa3*va.z + pb3*vb4.z;  acc3.w += pa3*va.w + pb3*vb4.w;

            if (!more) break;
            base += 16; kp += 512; vp += 512;
            ka = kna; va = vna; kb4 = knb; vb4 = vnb;
        }
    }

    __shared__ float4 sA4[8][GQ][32];
    __shared__ float  sL[8][GQ];
    sA4[w][0][lane] = acc0;
    sA4[w][1][lane] = acc1;
    sA4[w][2][lane] = acc2;
    sA4[w][3][lane] = acc3;
    if (lane < 4) sL[w][lane] = lsum;
    __syncthreads();

    const int obase = (pair * NSPLIT + split) * GQ;
    {
        const int half = tid >> 7;
        const int d    = tid & 127;
#pragma unroll
        for (int g = half; g < GQ; g += 2) {
            float A = 0.f;
#pragma unroll
            for (int ww = 0; ww < 8; ++ww)
                A += ((const float*)&sA4[ww][g][0])[d];
            g_pa[(obase + g) * D_HEAD + d] = A;
        }
        if (tid < 4) {
            float z = 0.f;
#pragma unroll
            for (int ww = 0; ww < 8; ++ww) z += sL[ww][tid];
            g_pl[obase + tid] = z;
        }
    }
}

// ---------------- 4) combine splits + new-token row -> ctx ---------------
// One warp per (pair, group); lanes = float4 d-chunks, NSPLIT unrolled loads.
__global__ void __launch_bounds__(256) k_attn_red() {
    const int W    = blockIdx.x * 8 + (threadIdx.x >> 5);   // (pair, g)
    const int lane = threadIdx.x & 31;
    const int pair = W >> 2, g = W & 3;
    const int b = pair >> 3, kv = pair & 7;

    float4 qv = *(const float4*)&g_q[((b * HQ) + kv * GQ + g) * D_HEAD + 4 * lane];
    float4 kn = *(const float4*)&g_k[pair * D_HEAD + 4 * lane];
    float s = qv.x*kn.x + qv.y*kn.y + qv.z*kn.z + qv.w*kn.w;
#pragma unroll
    for (int off = 16; off > 0; off >>= 1)
        s += __shfl_xor_sync(0xffffffffu, s, off);
    const float p = __expf(s * 0.08838834764831845f);

    float4 vn = *(const float4*)&g_v[pair * D_HEAD + 4 * lane];
    float Z = p;
    float4 A = make_float4(p * vn.x, p * vn.y, p * vn.z, p * vn.w);
#pragma unroll
    for (int sp = 0; sp < NSPLIT; ++sp) {
        int idx = (pair * NSPLIT + sp) * GQ + g;
        Z += g_pl[idx];
        float4 t = *(const float4*)&g_pa[idx * D_HEAD + 4 * lane];
        A.x += t.x; A.y += t.y; A.z += t.z; A.w += t.w;
    }
    const float inv = 1.f / Z;
    const int c = (kv * GQ + g) * D_HEAD + 4 * lane;
    *(float4*)&g_ctx[b * HID + c] = make_float4(A.x*inv, A.y*inv, A.z*inv, A.w*inv);
}

// ---------------- 5) sum wo K-split partials into the output (float4) -----
__global__ void k_addout(float* __restrict__ out) {
    int i = blockIdx.x * blockDim.x + threadIdx.x;   // BATCH*HID/4 threads
    float4 s = make_float4(0.f, 0.f, 0.f, 0.f);
#pragma unroll
    for (int k = 0; k < KS; ++k) {
        float4 t = *(const float4*)&g_op[k * BATCH * HID + 4 * i];
        s.x += t.x; s.y += t.y; s.z += t.z; s.w += t.w;
    }
    *(float4*)&out[4 * i] = s;
}

// ---------------- launch ----------------
extern "C" void kernel_launch(void* const* d_in, const int* in_sizes, int n_in,
                              void* d_out, int out_size) {
    const float* x    = (const float*)d_in[0];
    const float* wqkv = (const float*)d_in[1];
    const float* wo   = (const float*)d_in[2];
    const float* ck   = (const float*)d_in[3];
    const float* cv   = (const float*)d_in[4];
    const float* cosc = (const float*)d_in[5];
    const float* sinc = (const float*)d_in[6];
    // d_in[7] = attn_mask: equivalent to (pos <= start_pos), applied analytically
    const int* sp = (const int*)d_in[8];
    // d_in[9] = current_pos (== start_pos; new-token row handled in k_attn_red)
    float* out = (float*)d_out;

    static bool attr_set = false;
    if (!attr_set) {
        cudaFuncSetAttribute(k_gemm_tc,
                             cudaFuncAttributeMaxDynamicSharedMemorySize,
                             SMEM_GEMM);
        attr_set = true;
    }

    float* ctx; float* xp; float* op;
    cudaGetSymbolAddress((void**)&ctx, g_ctx);
    cudaGetSymbolAddress((void**)&xp,  g_xp);
    cudaGetSymbolAddress((void**)&op,  g_op);

    dim3 gq(QKV_COLS / 128, KS);
    k_gemm_tc<<<gq, 256, SMEM_GEMM>>>(x, wqkv, xp, QKV_COLS);
    k_rope<<<RPE_TOT / 256, 256>>>(cosc, sinc, sp);
    dim3 ag(NSPLIT, PAIRS);
    k_attn_part<<<ag, 256>>>(ck, cv, sp);
    k_attn_red<<<(PAIRS * GQ) / 8, 256>>>();
    dim3 go(HID / 128, KS);
    k_gemm_tc<<<go, 256, SMEM_GEMM>>>(ctx, wo, op, HID);
    k_addout<<<(BATCH * HID) / 1024, 256>>>(out);
}